// round 6
// baseline (speedup 1.0000x reference)
#include <cuda_runtime.h>
#include <math.h>

#define D 128
#define DD (D * D * D)
#define FULLMASK 0xFFFFFFFFu

__device__ __forceinline__ float4 ldg4(const float* __restrict__ p) {
    return __ldg(reinterpret_cast<const float4*>(p));
}

// Load one neighbor row segment (4 cells) + x-halo via shuffles.
// sentinel applied only when asked (x-position field) — it alone gates the
// warp-edge (periodic-wrap) pairs to zero force, matching the reference.
__device__ __forceinline__ void load_row(const float* __restrict__ p, int base,
                                         int lane, bool sentinel, float w[6]) {
    float4 v = ldg4(p + base);
    w[1] = v.x; w[2] = v.y; w[3] = v.z; w[4] = v.w;
    w[0] = __shfl_up_sync(FULLMASK, v.w, 1);
    w[5] = __shfl_down_sync(FULLMASK, v.x, 1);
    if (sentinel) {
        if (lane == 0)  w[0] = 1.0e8f;
        if (lane == 31) w[5] = 1.0e8f;
    }
}

// 12 spring-damper interactions: 4 center cells x 3 x-offsets against one
// neighbor row window w[6]. coef = (KN*(dist-PS) + ETA*(dv.d)/dc)/dc with
// dc = max(dist, 1e-4)  =>  1/dc = min(1/dist, 1e4) = min(rsqrt(d2), 1e4).
__device__ __forceinline__ void accum12(
    const float wx[6],  const float wy[6],  const float wz[6],
    const float wvx[6], const float wvy[6], const float wvz[6],
    const float cx[4],  const float cy[4],  const float cz[4],
    const float cvx[4], const float cvy[4], const float cvz[4],
    float fx[4], float fy[4], float fz[4], float eta)
{
#pragma unroll
    for (int i = 0; i < 4; ++i) {
#pragma unroll
        for (int o = 0; o < 3; ++o) {
            const int j = i + o;
            float d_x = cx[i] - wx[j];
            float d_y = cy[i] - wy[j];
            float d_z = cz[i] - wz[j];
            float d2  = fmaf(d_x, d_x, fmaf(d_y, d_y, d_z * d_z));
            float d2c = fmaxf(d2, 1e-12f);     // keeps self-pair finite
            float rs  = rsqrtf(d2c);
            float dist = d2c * rs;
            float rinv = fminf(rs, 1e4f);      // == 1/max(dist, 1e-4)
            float dvx = cvx[i] - wvx[j];
            float dvy = cvy[i] - wvy[j];
            float dvz = cvz[i] - wvz[j];
            float num = fmaf(dvx, d_x, fmaf(dvy, d_y, dvz * d_z));
            float ca  = fmaf(6.0e6f, dist, -6.0e5f);        // KN*(dist-PS)
            float cb  = fmaf(eta, num * rinv, ca);
            float coef = cb * rinv;
            if (d2 < 0.01f) {                  // dist < particle_size
                fx[i] = fmaf(coef, d_x, fx[i]);
                fy[i] = fmaf(coef, d_y, fy[i]);
                fz[i] = fmaf(coef, d_z, fz[i]);
            }
        }
    }
}

__device__ __forceinline__ float boundary_force(float p, float v, float mk, float eta) {
    float flo = (p > 0.1f && p < 0.15f) ? 1.0f : 0.0f;
    float fhi = (p > 12.65f) ? 1.0f : 0.0f;
    return 6.0e6f * flo * mk * (0.15f - p)
         - 6.0e6f * fhi * mk * (((p - 12.8f) + 0.1f) + 0.05f)
         - eta * v * flo * mk
         - eta * v * fhi * mk;
}

// One pass: update velocities of layer n. Each warp computes TWO adjacent
// center y-rows (yA, yB=yA+1); the 4 neighbor rows {yA-1..yA+2} per (dz,m)
// are loaded once and serve both centers (rows k=1,2 feed both).
__global__ void __launch_bounds__(128)
dem_pass(const float* __restrict__ xg, const float* __restrict__ yg,
         const float* __restrict__ zg,
         const float* __restrict__ v0x, const float* __restrict__ v0y,
         const float* __restrict__ v0z,
         const float* __restrict__ v1x, const float* __restrict__ v1y,
         const float* __restrict__ v1z,
         const float* __restrict__ mask,
         float* __restrict__ out,
         int n, float eta, float dt_pm, float g0)
{
    const int lane = threadIdx.x;                   // warp == x-row of 128 cells
    const int yA = blockIdx.y * 8 + threadIdx.y * 2;
    const int z  = blockIdx.z;
    const int x0 = lane << 2;
    const int idxA = (z * D + yA) * D + x0;
    const int idxB = idxA + D;
    const int nofs = n * DD;

    // Precompute the 4 neighbor y-row offsets (shared across dz and m).
    int yo[4];
#pragma unroll
    for (int k = 0; k < 4; ++k) yo[k] = (((yA - 1 + k) & (D - 1)) * D) + x0;

    const float* cvxp = n ? v1x : v0x;
    const float* cvyp = n ? v1y : v0y;
    const float* cvzp = n ? v1z : v0z;

    float cxA[4], cyA[4], czA[4], cvxA[4], cvyA[4], cvzA[4];
    float cxB[4], cyB[4], czB[4], cvxB[4], cvyB[4], cvzB[4];
    {
        float4 t;
        t = ldg4(xg + nofs + idxA);  cxA[0]=t.x; cxA[1]=t.y; cxA[2]=t.z; cxA[3]=t.w;
        t = ldg4(yg + nofs + idxA);  cyA[0]=t.x; cyA[1]=t.y; cyA[2]=t.z; cyA[3]=t.w;
        t = ldg4(zg + nofs + idxA);  czA[0]=t.x; czA[1]=t.y; czA[2]=t.z; czA[3]=t.w;
        t = ldg4(cvxp + idxA);       cvxA[0]=t.x; cvxA[1]=t.y; cvxA[2]=t.z; cvxA[3]=t.w;
        t = ldg4(cvyp + idxA);       cvyA[0]=t.x; cvyA[1]=t.y; cvyA[2]=t.z; cvyA[3]=t.w;
        t = ldg4(cvzp + idxA);       cvzA[0]=t.x; cvzA[1]=t.y; cvzA[2]=t.z; cvzA[3]=t.w;
        t = ldg4(xg + nofs + idxB);  cxB[0]=t.x; cxB[1]=t.y; cxB[2]=t.z; cxB[3]=t.w;
        t = ldg4(yg + nofs + idxB);  cyB[0]=t.x; cyB[1]=t.y; cyB[2]=t.z; cyB[3]=t.w;
        t = ldg4(zg + nofs + idxB);  czB[0]=t.x; czB[1]=t.y; czB[2]=t.z; czB[3]=t.w;
        t = ldg4(cvxp + idxB);       cvxB[0]=t.x; cvxB[1]=t.y; cvxB[2]=t.z; cvxB[3]=t.w;
        t = ldg4(cvyp + idxB);       cvyB[0]=t.x; cvyB[1]=t.y; cvyB[2]=t.z; cvyB[3]=t.w;
        t = ldg4(cvzp + idxB);       cvzB[0]=t.x; cvzB[1]=t.y; cvzB[2]=t.z; cvzB[3]=t.w;
    }

    float fxA[4] = {0,0,0,0}, fyA[4] = {0,0,0,0}, fzA[4] = {0,0,0,0};
    float fxB[4] = {0,0,0,0}, fyB[4] = {0,0,0,0}, fzB[4] = {0,0,0,0};

#pragma unroll 1
    for (int dz = -1; dz <= 1; ++dz) {
        const int zrow = ((z + dz) & (D - 1)) * (D * D);
#pragma unroll 1
        for (int m = 0; m < 2; ++m) {
            const int mo = m * DD;
            const float* px  = xg + mo;
            const float* py  = yg + mo;
            const float* pz  = zg + mo;
            const float* pvx = m ? v1x : v0x;
            const float* pvy = m ? v1y : v0y;
            const float* pvz = m ? v1z : v0z;
#pragma unroll
            for (int k = 0; k < 4; ++k) {
                const int base = zrow + yo[k];
                float wx[6], wy[6], wz[6], wvx[6], wvy[6], wvz[6];
                load_row(px,  base, lane, true,  wx);
                load_row(py,  base, lane, false, wy);
                load_row(pz,  base, lane, false, wz);
                load_row(pvx, base, lane, false, wvx);
                load_row(pvy, base, lane, false, wvy);
                load_row(pvz, base, lane, false, wvz);
                if (k < 3)
                    accum12(wx, wy, wz, wvx, wvy, wvz,
                            cxA, cyA, czA, cvxA, cvyA, cvzA,
                            fxA, fyA, fzA, eta);
                if (k > 0)
                    accum12(wx, wy, wz, wvx, wvy, wvz,
                            cxB, cyB, czB, cvxB, cvyB, cvzB,
                            fxB, fyB, fzB, eta);
            }
        }
    }

    // Epilogue: boundary + velocity update + store, for both rows.
    float4 mkA4 = ldg4(mask + nofs + idxA);
    float4 mkB4 = ldg4(mask + nofs + idxB);
    float mkA[4] = {mkA4.x, mkA4.y, mkA4.z, mkA4.w};
    float mkB[4] = {mkB4.x, mkB4.y, mkB4.z, mkB4.w};

    float oxA[4], oyA[4], ozA[4], oxB[4], oyB[4], ozB[4];
#pragma unroll
    for (int i = 0; i < 4; ++i) {
        float tA = dt_pm * mkA[i];
        oxA[i] = cvxA[i] + tA * (boundary_force(cxA[i], cvxA[i], mkA[i], eta) - fxA[i]);
        oyA[i] = cvyA[i] + tA * (boundary_force(cyA[i], cvyA[i], mkA[i], eta) - fyA[i]);
        ozA[i] = cvzA[i] + tA * ((g0 - fzA[i]) + boundary_force(czA[i], cvzA[i], mkA[i], eta));
        float tB = dt_pm * mkB[i];
        oxB[i] = cvxB[i] + tB * (boundary_force(cxB[i], cvxB[i], mkB[i], eta) - fxB[i]);
        oyB[i] = cvyB[i] + tB * (boundary_force(cyB[i], cvyB[i], mkB[i], eta) - fyB[i]);
        ozB[i] = cvzB[i] + tB * ((g0 - fzB[i]) + boundary_force(czB[i], cvzB[i], mkB[i], eta));
    }

    *reinterpret_cast<float4*>(out + (0 * 2 + n) * DD + idxA) = make_float4(oxA[0], oxA[1], oxA[2], oxA[3]);
    *reinterpret_cast<float4*>(out + (1 * 2 + n) * DD + idxA) = make_float4(oyA[0], oyA[1], oyA[2], oyA[3]);
    *reinterpret_cast<float4*>(out + (2 * 2 + n) * DD + idxA) = make_float4(ozA[0], ozA[1], ozA[2], ozA[3]);
    *reinterpret_cast<float4*>(out + (0 * 2 + n) * DD + idxB) = make_float4(oxB[0], oxB[1], oxB[2], oxB[3]);
    *reinterpret_cast<float4*>(out + (1 * 2 + n) * DD + idxB) = make_float4(oyB[0], oyB[1], oyB[2], oyB[3]);
    *reinterpret_cast<float4*>(out + (2 * 2 + n) * DD + idxB) = make_float4(ozB[0], ozB[1], ozB[2], ozB[3]);
}

extern "C" void kernel_launch(void* const* d_in, const int* in_sizes, int n_in,
                              void* d_out, int out_size)
{
    const float* xg   = (const float*)d_in[0];
    const float* yg   = (const float*)d_in[1];
    const float* zg   = (const float*)d_in[2];
    const float* vx   = (const float*)d_in[3];
    const float* vy   = (const float*)d_in[4];
    const float* vz   = (const float*)d_in[5];
    const float* mask = (const float*)d_in[6];
    float* out = (float*)d_out;

    const double PM    = 4.0 / 3.0 * 3.1415 * (0.1 * 0.1 * 0.1) * 2700.0;
    const double alpha = 0.6931471805599453 / 3.141592653589793;  // -log(0.5)/pi
    const double gamma = alpha / sqrt(alpha * alpha + 1.0);
    const float eta    = (float)(2.0 * gamma * sqrt(6.0e6 * PM));
    const float dt_pm  = (float)(1e-4 / PM);
    const float g0     = (float)(-9.8 * PM);

    dim3 blk(32, 4, 1);
    dim3 grd(1, D / 8, D);   // each warp: 2 y-rows; block: 8 y-rows

    // Pass n=0: both neighbor velocity layers come from the inputs.
    dem_pass<<<grd, blk>>>(xg, yg, zg,
                           vx, vy, vz,
                           vx + DD, vy + DD, vz + DD,
                           mask, out, 0, eta, dt_pm, g0);

    // Pass n=1: layer-0 velocities are the just-updated ones living in out.
    dem_pass<<<grd, blk>>>(xg, yg, zg,
                           out + 0 * 2 * DD, out + 1 * 2 * DD, out + 2 * 2 * DD,
                           vx + DD, vy + DD, vz + DD,
                           mask, out, 1, eta, dt_pm, g0);
}

// round 15
// speedup vs baseline: 1.1972x; 1.1972x over previous
#include <cuda_runtime.h>
#include <math.h>

#define D 128
#define DD (D * D * D)
#define FULLMASK 0xFFFFFFFFu

__device__ __forceinline__ float4 ldg4(const float* __restrict__ p) {
    return __ldg(reinterpret_cast<const float4*>(p));
}

// Accumulate contact forces from one particle layer over the 9 precomputed
// neighbor rows (3x3 in y/z) x 3 x-offsets. Each thread owns 4 consecutive
// x-cells; warp (32 threads) covers one full 128-cell row. x-halo via warp
// shuffles; warp-edge x-neighbors are the reference's periodic-wrap pairs
// (dist ~ 12.7 -> zero force), emulated with a 1e8 position sentinel.
__device__ __forceinline__ void layer_accum(
    const float* __restrict__ px,  const float* __restrict__ py,
    const float* __restrict__ pz,  const float* __restrict__ pvx,
    const float* __restrict__ pvy, const float* __restrict__ pvz,
    const int* bases, int lane, float eta,
    const float* cx, const float* cy, const float* cz,
    const float* cvx, const float* cvy, const float* cvz,
    float* fx, float* fy, float* fz)
{
#pragma unroll 1
    for (int r = 0; r < 9; ++r) {
        const int base = bases[r];

        float4 nx4  = ldg4(px  + base);
        float4 ny4  = ldg4(py  + base);
        float4 nz4  = ldg4(pz  + base);
        float4 nvx4 = ldg4(pvx + base);
        float4 nvy4 = ldg4(pvy + base);
        float4 nvz4 = ldg4(pvz + base);

        float wx[6], wy[6], wz[6], wvx[6], wvy[6], wvz[6];
        wx[1] = nx4.x;  wx[2] = nx4.y;  wx[3] = nx4.z;  wx[4] = nx4.w;
        wy[1] = ny4.x;  wy[2] = ny4.y;  wy[3] = ny4.z;  wy[4] = ny4.w;
        wz[1] = nz4.x;  wz[2] = nz4.y;  wz[3] = nz4.z;  wz[4] = nz4.w;
        wvx[1] = nvx4.x; wvx[2] = nvx4.y; wvx[3] = nvx4.z; wvx[4] = nvx4.w;
        wvy[1] = nvy4.x; wvy[2] = nvy4.y; wvy[3] = nvy4.z; wvy[4] = nvy4.w;
        wvz[1] = nvz4.x; wvz[2] = nvz4.y; wvz[3] = nvz4.z; wvz[4] = nvz4.w;

        wx[0]  = __shfl_up_sync(FULLMASK, nx4.w, 1);
        wy[0]  = __shfl_up_sync(FULLMASK, ny4.w, 1);
        wz[0]  = __shfl_up_sync(FULLMASK, nz4.w, 1);
        wvx[0] = __shfl_up_sync(FULLMASK, nvx4.w, 1);
        wvy[0] = __shfl_up_sync(FULLMASK, nvy4.w, 1);
        wvz[0] = __shfl_up_sync(FULLMASK, nvz4.w, 1);

        wx[5]  = __shfl_down_sync(FULLMASK, nx4.x, 1);
        wy[5]  = __shfl_down_sync(FULLMASK, ny4.x, 1);
        wz[5]  = __shfl_down_sync(FULLMASK, nz4.x, 1);
        wvx[5] = __shfl_down_sync(FULLMASK, nvx4.x, 1);
        wvy[5] = __shfl_down_sync(FULLMASK, nvy4.x, 1);
        wvz[5] = __shfl_down_sync(FULLMASK, nvz4.x, 1);

        // x-sentinel alone gates the warp-edge pair to zero force.
        if (lane == 0)  wx[0] = 1.0e8f;
        if (lane == 31) wx[5] = 1.0e8f;

#pragma unroll
        for (int i = 0; i < 4; ++i) {
#pragma unroll
            for (int o = 0; o < 3; ++o) {
                const int j = i + o;   // neighbor at x offset o-1
                float d_x = cx[i] - wx[j];
                float d_y = cy[i] - wy[j];
                float d_z = cz[i] - wz[j];
                float d2  = fmaf(d_x, d_x, fmaf(d_y, d_y, d_z * d_z));
                float d2c = fmaxf(d2, 1e-12f);   // keeps self-pair finite
                float rs   = rsqrtf(d2c);
                float dist = d2c * rs;
                float rinv = fminf(rs, 1e4f);    // == 1/max(dist, 1e-4)
                float dvx = cvx[i] - wvx[j];
                float dvy = cvy[i] - wvy[j];
                float dvz = cvz[i] - wvz[j];
                float num = fmaf(dvx, d_x, fmaf(dvy, d_y, dvz * d_z));
                float ca  = fmaf(6.0e6f, dist, -6.0e5f);   // KN*(dist-PS)
                float cb  = fmaf(eta, num * rinv, ca);
                float coef = cb * rinv;
                if (d2 < 0.01f) {                // dist < particle_size
                    fx[i] = fmaf(coef, d_x, fx[i]);
                    fy[i] = fmaf(coef, d_y, fy[i]);
                    fz[i] = fmaf(coef, d_z, fz[i]);
                }
            }
        }
    }
}

__device__ __forceinline__ float boundary_force(float p, float v, float mk, float eta) {
    float flo = (p > 0.1f && p < 0.15f) ? 1.0f : 0.0f;
    float fhi = (p > 12.65f) ? 1.0f : 0.0f;
    return 6.0e6f * flo * mk * (0.15f - p)
         - 6.0e6f * fhi * mk * (((p - 12.8f) + 0.1f) + 0.05f)
         - eta * v * flo * mk
         - eta * v * fhi * mk;
}

__global__ void __launch_bounds__(128)
dem_pass(const float* __restrict__ xg, const float* __restrict__ yg,
         const float* __restrict__ zg,
         const float* __restrict__ v0x, const float* __restrict__ v0y,
         const float* __restrict__ v0z,
         const float* __restrict__ v1x, const float* __restrict__ v1y,
         const float* __restrict__ v1z,
         const float* __restrict__ mask,
         float* __restrict__ out,
         int n, float eta, float dt_pm, float g0)
{
    const int lane = threadIdx.x;                       // 0..31, warp == one row
    const int y = blockIdx.y * 4 + threadIdx.y;         // blockDim = (32,4,1)
    const int z = blockIdx.z;
    const int x0 = lane << 2;
    const int idxc = (z * D + y) * D + x0;
    const int nofs = n * DD;

    // Hoist the 9 neighbor-row base offsets (shared across both layers).
    int bases[9];
#pragma unroll
    for (int r = 0; r < 9; ++r) {
        const int dzo = r / 3 - 1;
        const int dyo = r % 3 - 1;
        const int zz = (z + dzo) & (D - 1);
        const int yy = (y + dyo) & (D - 1);
        bases[r] = (zz * D + yy) * D + x0;
    }

    float4 cx4 = ldg4(xg + nofs + idxc);
    float4 cy4 = ldg4(yg + nofs + idxc);
    float4 cz4 = ldg4(zg + nofs + idxc);
    const float* cvxp = n ? v1x : v0x;
    const float* cvyp = n ? v1y : v0y;
    const float* cvzp = n ? v1z : v0z;
    float4 cvx4 = ldg4(cvxp + idxc);
    float4 cvy4 = ldg4(cvyp + idxc);
    float4 cvz4 = ldg4(cvzp + idxc);

    float cx[4]  = {cx4.x,  cx4.y,  cx4.z,  cx4.w};
    float cy[4]  = {cy4.x,  cy4.y,  cy4.z,  cy4.w};
    float cz[4]  = {cz4.x,  cz4.y,  cz4.z,  cz4.w};
    float cvx[4] = {cvx4.x, cvx4.y, cvx4.z, cvx4.w};
    float cvy[4] = {cvy4.x, cvy4.y, cvy4.z, cvy4.w};
    float cvz[4] = {cvz4.x, cvz4.y, cvz4.z, cvz4.w};

    float fx[4] = {0.f, 0.f, 0.f, 0.f};
    float fy[4] = {0.f, 0.f, 0.f, 0.f};
    float fz[4] = {0.f, 0.f, 0.f, 0.f};

    // m = 0 layer, then m = 1 layer
    layer_accum(xg,      yg,      zg,      v0x, v0y, v0z,
                bases, lane, eta, cx, cy, cz, cvx, cvy, cvz, fx, fy, fz);
    layer_accum(xg + DD, yg + DD, zg + DD, v1x, v1y, v1z,
                bases, lane, eta, cx, cy, cz, cvx, cvy, cvz, fx, fy, fz);

    float4 mk4 = ldg4(mask + nofs + idxc);
    float mk[4] = {mk4.x, mk4.y, mk4.z, mk4.w};

    float ox[4], oy[4], oz[4];
#pragma unroll
    for (int i = 0; i < 4; ++i) {
        float t = dt_pm * mk[i];
        float fbx = boundary_force(cx[i], cvx[i], mk[i], eta);
        float fby = boundary_force(cy[i], cvy[i], mk[i], eta);
        float fbz = boundary_force(cz[i], cvz[i], mk[i], eta);
        ox[i] = cvx[i] + t * (fbx - fx[i]);
        oy[i] = cvy[i] + t * (fby - fy[i]);
        oz[i] = cvz[i] + t * ((g0 - fz[i]) + fbz);
    }

    *reinterpret_cast<float4*>(out + (0 * 2 + n) * DD + idxc) =
        make_float4(ox[0], ox[1], ox[2], ox[3]);
    *reinterpret_cast<float4*>(out + (1 * 2 + n) * DD + idxc) =
        make_float4(oy[0], oy[1], oy[2], oy[3]);
    *reinterpret_cast<float4*>(out + (2 * 2 + n) * DD + idxc) =
        make_float4(oz[0], oz[1], oz[2], oz[3]);
}

extern "C" void kernel_launch(void* const* d_in, const int* in_sizes, int n_in,
                              void* d_out, int out_size)
{
    const float* xg   = (const float*)d_in[0];
    const float* yg   = (const float*)d_in[1];
    const float* zg   = (const float*)d_in[2];
    const float* vx   = (const float*)d_in[3];
    const float* vy   = (const float*)d_in[4];
    const float* vz   = (const float*)d_in[5];
    const float* mask = (const float*)d_in[6];
    float* out = (float*)d_out;

    const double PM    = 4.0 / 3.0 * 3.1415 * (0.1 * 0.1 * 0.1) * 2700.0;
    const double alpha = 0.6931471805599453 / 3.141592653589793;  // -log(0.5)/pi
    const double gamma = alpha / sqrt(alpha * alpha + 1.0);
    const float eta    = (float)(2.0 * gamma * sqrt(6.0e6 * PM));
    const float dt_pm  = (float)(1e-4 / PM);
    const float g0     = (float)(-9.8 * PM);

    dim3 blk(32, 4, 1);
    dim3 grd(1, D / 4, D);

    // Pass n=0: both velocity layers come from the inputs.
    dem_pass<<<grd, blk>>>(xg, yg, zg,
                           vx, vy, vz,
                           vx + DD, vy + DD, vz + DD,
                           mask, out, 0, eta, dt_pm, g0);

    // Pass n=1: layer-0 velocities are the just-updated ones living in out.
    dem_pass<<<grd, blk>>>(xg, yg, zg,
                           out + 0 * 2 * DD, out + 1 * 2 * DD, out + 2 * 2 * DD,
                           vx + DD, vy + DD, vz + DD,
                           mask, out, 1, eta, dt_pm, g0);
}